// round 2
// baseline (speedup 1.0000x reference)
#include <cuda_runtime.h>
#include <math.h>

// Problem constants
#define NB 1024
#define ND 512
#define NC 100000

static constexpr float S_SCALE = 30.0f;
static constexpr float COS_M   = 0.9553364891256060f;   // cos(0.3)
static constexpr float SIN_M   = 0.2955202066613396f;   // sin(0.3)
static constexpr float TH      = -0.9553364891256060f;  // cos(pi-0.3)
static constexpr float MM      = 0.0886560619984019f;   // sin(pi-0.3)*0.3
static constexpr float EPS     = 1e-12f;

// GEMM tiling
static constexpr int BM = 64;
static constexpr int BN = 64;
static constexpr int BK = 16;
static constexpr int NCHUNK = (NC + BN - 1) / BN;  // 1563

// Scratch (allocation-free rule: __device__ globals)
__device__ float g_fhat[NB * ND];        // normalized features, 2 MB
__device__ float g_winv[NC];             // 1/||w_c||, 400 KB
__device__ float g_pm[NB * NCHUNK];      // per (row, col-chunk) running max of s*cos
__device__ float g_ps[NB * NCHUNK];      // per (row, col-chunk) sum of exp
__device__ float g_lse[NB];              // per-row logsumexp over ALL raw logits
__device__ float g_cost[NB];             // per-row target cosine

// ---------------------------------------------------------------------------
// Kernel 1: normalize features. grid=1024, block=128 (each thread one float4)
// ---------------------------------------------------------------------------
__global__ void k_norm_feat(const float* __restrict__ f) {
    int b = blockIdx.x;
    int t = threadIdx.x;  // 0..127
    float4 v = reinterpret_cast<const float4*>(f + (size_t)b * ND)[t];
    float ss = v.x * v.x + v.y * v.y + v.z * v.z + v.w * v.w;
    #pragma unroll
    for (int o = 16; o; o >>= 1) ss += __shfl_xor_sync(0xFFFFFFFFu, ss, o);
    __shared__ float sw[4];
    if ((t & 31) == 0) sw[t >> 5] = ss;
    __syncthreads();
    float tot = sw[0] + sw[1] + sw[2] + sw[3];
    float inv = 1.0f / fmaxf(sqrtf(tot), EPS);
    float4 o4 = make_float4(v.x * inv, v.y * inv, v.z * inv, v.w * inv);
    reinterpret_cast<float4*>(g_fhat + (size_t)b * ND)[t] = o4;
}

// ---------------------------------------------------------------------------
// Kernel 2: weight inverse norms. One warp per weight row.
// ---------------------------------------------------------------------------
__global__ void k_winv(const float* __restrict__ w) {
    int row = blockIdx.x * 8 + (threadIdx.x >> 5);
    if (row >= NC) return;
    int lane = threadIdx.x & 31;
    const float4* p = reinterpret_cast<const float4*>(w + (size_t)row * ND);
    float ss = 0.0f;
    #pragma unroll
    for (int i = 0; i < 4; i++) {
        float4 v = p[lane + i * 32];
        ss += v.x * v.x + v.y * v.y + v.z * v.z + v.w * v.w;
    }
    #pragma unroll
    for (int o = 16; o; o >>= 1) ss += __shfl_xor_sync(0xFFFFFFFFu, ss, o);
    if (lane == 0) g_winv[row] = 1.0f / fmaxf(sqrtf(ss), EPS);
}

// ---------------------------------------------------------------------------
// Kernel 3: fused GEMM + per-tile online softmax partials.
// grid = (NCHUNK, NB/BM), block = 256 threads (16x16, each 4x4 accum)
// ---------------------------------------------------------------------------
__global__ void __launch_bounds__(256) k_gemm(const float* __restrict__ w) {
    __shared__ float As[BK][BM];
    __shared__ float Bs[BK][BN];

    const int chunk   = blockIdx.x;
    const int rowBase = blockIdx.y * BM;
    const int colBase = chunk * BN;
    const int tid = threadIdx.x;
    const int ty = tid >> 4;        // 0..15
    const int tx = tid & 15;        // 0..15

    // loader mapping: each thread loads one float4 of A and one of B per stage
    const int lr = tid >> 2;            // 0..63 (tile row / tile col)
    const int lk = (tid & 3) * 4;       // 0,4,8,12

    const int gcLoad = colBase + lr;
    const bool gcValid = (gcLoad < NC);
    const float* aPtr = g_fhat + (size_t)(rowBase + lr) * ND + lk;
    const float* bPtr = gcValid ? (w + (size_t)gcLoad * ND + lk) : nullptr;

    float acc[4][4] = {};

    for (int k0 = 0; k0 < ND; k0 += BK) {
        float4 av = *reinterpret_cast<const float4*>(aPtr + k0);
        float4 bv = make_float4(0.f, 0.f, 0.f, 0.f);
        if (gcValid) bv = *reinterpret_cast<const float4*>(bPtr + k0);
        __syncthreads();
        As[lk + 0][lr] = av.x; As[lk + 1][lr] = av.y;
        As[lk + 2][lr] = av.z; As[lk + 3][lr] = av.w;
        Bs[lk + 0][lr] = bv.x; Bs[lk + 1][lr] = bv.y;
        Bs[lk + 2][lr] = bv.z; Bs[lk + 3][lr] = bv.w;
        __syncthreads();
        #pragma unroll
        for (int k = 0; k < BK; k++) {
            float4 a = *reinterpret_cast<const float4*>(&As[k][ty * 4]);
            float4 b = *reinterpret_cast<const float4*>(&Bs[k][tx * 4]);
            acc[0][0] += a.x * b.x; acc[0][1] += a.x * b.y; acc[0][2] += a.x * b.z; acc[0][3] += a.x * b.w;
            acc[1][0] += a.y * b.x; acc[1][1] += a.y * b.y; acc[1][2] += a.y * b.z; acc[1][3] += a.y * b.w;
            acc[2][0] += a.z * b.x; acc[2][1] += a.z * b.y; acc[2][2] += a.z * b.z; acc[2][3] += a.z * b.w;
            acc[3][0] += a.w * b.x; acc[3][1] += a.w * b.y; acc[3][2] += a.w * b.z; acc[3][3] += a.w * b.w;
        }
    }

    // epilogue: logits = S * cos = S * acc * winv[col]; reduce (max,sumexp) per row
    float winv4[4];
    bool  valid[4];
    #pragma unroll
    for (int j = 0; j < 4; j++) {
        int gc = colBase + tx * 4 + j;
        valid[j] = (gc < NC);
        winv4[j] = valid[j] ? g_winv[gc] : 0.0f;
    }

    #pragma unroll
    for (int i = 0; i < 4; i++) {
        float v[4];
        float m = -INFINITY;
        #pragma unroll
        for (int j = 0; j < 4; j++) {
            v[j] = valid[j] ? (S_SCALE * acc[i][j] * winv4[j]) : -INFINITY;
            m = fmaxf(m, v[j]);
        }
        float ssum = 0.0f;
        if (m > -INFINITY) {
            #pragma unroll
            for (int j = 0; j < 4; j++) ssum += __expf(v[j] - m);  // exp(-inf)=0 ok
        }
        // merge across the 16 tx lanes (xor stays within 16-lane group)
        #pragma unroll
        for (int o = 8; o; o >>= 1) {
            float m2 = __shfl_xor_sync(0xFFFFFFFFu, m, o);
            float s2 = __shfl_xor_sync(0xFFFFFFFFu, ssum, o);
            float M = fmaxf(m, m2);
            ssum = (M == -INFINITY) ? 0.0f
                 : ssum * __expf(m - M) + s2 * __expf(m2 - M);
            m = M;
        }
        if (tx == 0) {
            int grow = rowBase + ty * 4 + i;
            g_pm[(size_t)grow * NCHUNK + chunk] = m;
            g_ps[(size_t)grow * NCHUNK + chunk] = ssum;
        }
    }
}

// ---------------------------------------------------------------------------
// Kernel 4: target-column cosine. grid=1024 (one row each), block=128
// NOTE: targets are int32 (JAX canonicalizes int64 -> int32 with x64 disabled)
// ---------------------------------------------------------------------------
__global__ void k_cost(const float* __restrict__ w,
                       const int* __restrict__ tgt) {
    int b = blockIdx.x;
    int t = threadIdx.x;  // 0..127
    int c = tgt[b];
    float4 f = reinterpret_cast<const float4*>(g_fhat + (size_t)b * ND)[t];
    float4 ww = reinterpret_cast<const float4*>(w + (size_t)c * ND)[t];
    float d = f.x * ww.x + f.y * ww.y + f.z * ww.z + f.w * ww.w;
    #pragma unroll
    for (int o = 16; o; o >>= 1) d += __shfl_xor_sync(0xFFFFFFFFu, d, o);
    __shared__ float sw[4];
    if ((t & 31) == 0) sw[t >> 5] = d;
    __syncthreads();
    if (t == 0) {
        float tot = sw[0] + sw[1] + sw[2] + sw[3];
        g_cost[b] = tot * g_winv[c];
    }
}

// ---------------------------------------------------------------------------
// Kernel 5: combine per-chunk partials into per-row LSE. grid=1024, block=256
// ---------------------------------------------------------------------------
__global__ void k_lse() {
    int row = blockIdx.x;
    int t = threadIdx.x;  // 0..255
    float m = -INFINITY, s = 0.0f;
    for (int c = t; c < NCHUNK; c += 256) {
        float m2 = g_pm[(size_t)row * NCHUNK + c];
        float s2 = g_ps[(size_t)row * NCHUNK + c];
        float M = fmaxf(m, m2);
        s = (M == -INFINITY) ? 0.0f : s * __expf(m - M) + s2 * __expf(m2 - M);
        m = M;
    }
    // warp merge
    #pragma unroll
    for (int o = 16; o; o >>= 1) {
        float m2 = __shfl_xor_sync(0xFFFFFFFFu, m, o);
        float s2 = __shfl_xor_sync(0xFFFFFFFFu, s, o);
        float M = fmaxf(m, m2);
        s = (M == -INFINITY) ? 0.0f : s * __expf(m - M) + s2 * __expf(m2 - M);
        m = M;
    }
    __shared__ float sm[8], ss[8];
    if ((t & 31) == 0) { sm[t >> 5] = m; ss[t >> 5] = s; }
    __syncthreads();
    if (t == 0) {
        float M = sm[0];
        #pragma unroll
        for (int i = 1; i < 8; i++) M = fmaxf(M, sm[i]);
        float tot = 0.0f;
        #pragma unroll
        for (int i = 0; i < 8; i++) tot += ss[i] * __expf(sm[i] - M);
        g_lse[row] = M + logf(tot);
    }
}

// ---------------------------------------------------------------------------
// Kernel 6: margin correction + CE mean. single block 256 threads
// ---------------------------------------------------------------------------
__global__ void k_loss(float* __restrict__ out) {
    int t = threadIdx.x;
    float acc = 0.0f;
    for (int b = t; b < NB; b += 256) {
        float c = g_cost[b];
        float sine = sqrtf(fmaxf(1.0f - c * c, 0.0f));
        float phi = c * COS_M - sine * SIN_M;
        if (!(c > TH)) phi = c - MM;
        float L  = g_lse[b];
        float lt = S_SCALE * phi;
        float lc = S_SCALE * c;
        // replace target's raw logit with margin logit inside the LSE
        float corr = log1pf(expf(lt - L) - expf(lc - L));
        acc += (L + corr) - lt;
    }
    #pragma unroll
    for (int o = 16; o; o >>= 1) acc += __shfl_xor_sync(0xFFFFFFFFu, acc, o);
    __shared__ float sw[8];
    if ((t & 31) == 0) sw[t >> 5] = acc;
    __syncthreads();
    if (t == 0) {
        float tot = 0.0f;
        #pragma unroll
        for (int i = 0; i < 8; i++) tot += sw[i];
        out[0] = tot / (float)NB;
    }
}

// ---------------------------------------------------------------------------
extern "C" void kernel_launch(void* const* d_in, const int* in_sizes, int n_in,
                              void* d_out, int out_size) {
    const float* feat = (const float*)d_in[0];   // [1024, 512] f32
    const float* wt   = (const float*)d_in[1];   // [100000, 512] f32
    const int*   tgt  = (const int*)d_in[2];     // [1024] int32
    float* out = (float*)d_out;

    k_norm_feat<<<NB, 128>>>(feat);
    k_winv<<<(NC + 7) / 8, 256>>>(wt);
    k_gemm<<<dim3(NCHUNK, NB / BM), 256>>>(wt);
    k_cost<<<NB, 128>>>(wt, tgt);
    k_lse<<<NB, 256>>>();
    k_loss<<<1, 256>>>(out);
}

// round 4
// speedup vs baseline: 7.8837x; 7.8837x over previous
#include <cuda_runtime.h>
#include <cuda_bf16.h>
#include <math.h>
#include <stdint.h>

// Problem constants
#define NB 1024
#define ND 512
#define NC 100000

static constexpr float S_SCALE = 30.0f;
static constexpr float COS_M   = 0.9553364891256060f;   // cos(0.3)
static constexpr float SIN_M   = 0.2955202066613396f;   // sin(0.3)
static constexpr float TH      = -0.9553364891256060f;  // cos(pi-0.3)
static constexpr float MM      = 0.0886560619984019f;   // sin(pi-0.3)*0.3
static constexpr float EPS     = 1e-12f;
static constexpr float LOG2E   = 1.4426950408889634f;
static constexpr float K1      = S_SCALE * LOG2E;        // exp(30c-30) = 2^(c*K1 + K0)
static constexpr float K0      = -S_SCALE * LOG2E;

// GEMM tiling
static constexpr int BN     = 128;                 // classes per CTA
static constexpr int NCHUNK = (NC + BN - 1) / BN;  // 782
static constexpr int SLICE_M = 256;                // rows per m-slice
static constexpr int NSLICE  = NB / SLICE_M;       // 4
static constexpr int BK     = 64;                  // K per A smem tile
static constexpr int NKS    = ND / BK;             // 8
static constexpr int NT     = NSLICE * NKS;        // 32 flat tiles

// smem geometry (bytes)
static constexpr int B_ROW   = 1040;               // 1024 data + 16 pad (conflict-free ldmatrix)
static constexpr int A_ROW   = 144;                // 128 data + 16 pad
static constexpr int SZ_B    = BN * B_ROW;         // 133120
static constexpr int A_STRIDE = SLICE_M * A_ROW;   // 36864 per buffer
static constexpr int SM_TOTAL = SZ_B + 2 * A_STRIDE;  // 206848

// Scratch (__device__ globals; no runtime alloc allowed)
__device__ float          g_fhat[NB * ND];              // normalized features fp32 (exact k_cost)
__device__ __nv_bfloat16  g_fhat_b[NB * ND];            // normalized features bf16
__device__ __nv_bfloat16  g_wb[(size_t)NC * ND];        // normalized weights bf16 (~100 MB)
__device__ float          g_winv[NC];                   // 1/||w_c||
__device__ float          g_ps[2][(size_t)NB * NCHUNK]; // per (plane,row,chunk) sum of exp(v-30)
__device__ float          g_lse[NB];
__device__ float          g_cost[NB];

// ---------------------------------------------------------------------------
// PTX helpers (plain sm_103 ISA only: ldmatrix / mma.sync / cp.async)
// ---------------------------------------------------------------------------
__device__ __forceinline__ uint32_t smem_u32(const void* p) {
    uint32_t a;
    asm("{ .reg .u64 t; cvta.to.shared.u64 t, %1; cvt.u32.u64 %0, t; }" : "=r"(a) : "l"(p));
    return a;
}

#define LDSM_X4(r0, r1, r2, r3, addr) \
    asm volatile("ldmatrix.sync.aligned.m8n8.x4.shared.b16 {%0,%1,%2,%3}, [%4];" \
                 : "=r"(r0), "=r"(r1), "=r"(r2), "=r"(r3) : "r"(addr))

#define MMA_BF16(d, a, b0, b1) \
    asm volatile("mma.sync.aligned.m16n8k16.row.col.f32.bf16.bf16.f32 " \
                 "{%0,%1,%2,%3}, {%4,%5,%6,%7}, {%8,%9}, {%0,%1,%2,%3};" \
                 : "+f"((d)[0]), "+f"((d)[1]), "+f"((d)[2]), "+f"((d)[3]) \
                 : "r"((a)[0]), "r"((a)[1]), "r"((a)[2]), "r"((a)[3]), \
                   "r"(b0), "r"(b1))

#define CP16(dst, src) \
    asm volatile("cp.async.cg.shared.global [%0], [%1], 16;" :: "r"(dst), "l"(src))
#define CP16Z(dst, src, sz) \
    asm volatile("cp.async.cg.shared.global [%0], [%1], 16, %2;" :: "r"(dst), "l"(src), "r"(sz))
#define CP_COMMIT() asm volatile("cp.async.commit_group;" ::: "memory")

// ---------------------------------------------------------------------------
// Kernel 1: normalize features -> fp32 + bf16. grid=1024, block=128
// ---------------------------------------------------------------------------
__global__ void k_norm_feat(const float* __restrict__ f) {
    int b = blockIdx.x;
    int t = threadIdx.x;
    float4 v = reinterpret_cast<const float4*>(f + (size_t)b * ND)[t];
    float ss = v.x * v.x + v.y * v.y + v.z * v.z + v.w * v.w;
    #pragma unroll
    for (int o = 16; o; o >>= 1) ss += __shfl_xor_sync(0xFFFFFFFFu, ss, o);
    __shared__ float sw[4];
    if ((t & 31) == 0) sw[t >> 5] = ss;
    __syncthreads();
    float tot = sw[0] + sw[1] + sw[2] + sw[3];
    float inv = 1.0f / fmaxf(sqrtf(tot), EPS);
    float4 o4 = make_float4(v.x * inv, v.y * inv, v.z * inv, v.w * inv);
    reinterpret_cast<float4*>(g_fhat + (size_t)b * ND)[t] = o4;
    __nv_bfloat162 p0 = __floats2bfloat162_rn(o4.x, o4.y);
    __nv_bfloat162 p1 = __floats2bfloat162_rn(o4.z, o4.w);
    uint2 u;
    u.x = *reinterpret_cast<uint32_t*>(&p0);
    u.y = *reinterpret_cast<uint32_t*>(&p1);
    reinterpret_cast<uint2*>(g_fhat_b + (size_t)b * ND)[t] = u;
}

// ---------------------------------------------------------------------------
// Kernel 2: weight norms + normalized bf16 copy. One warp per row.
// ---------------------------------------------------------------------------
__global__ void k_wconv(const float* __restrict__ w) {
    int row = blockIdx.x * 8 + (threadIdx.x >> 5);
    if (row >= NC) return;
    int lane = threadIdx.x & 31;
    const float4* p = reinterpret_cast<const float4*>(w + (size_t)row * ND);
    float4 v[4];
    float ss = 0.0f;
    #pragma unroll
    for (int i = 0; i < 4; i++) {
        v[i] = p[lane + i * 32];
        ss += v[i].x * v[i].x + v[i].y * v[i].y + v[i].z * v[i].z + v[i].w * v[i].w;
    }
    #pragma unroll
    for (int o = 16; o; o >>= 1) ss += __shfl_xor_sync(0xFFFFFFFFu, ss, o);
    float winv = 1.0f / fmaxf(sqrtf(ss), EPS);
    if (lane == 0) g_winv[row] = winv;
    #pragma unroll
    for (int i = 0; i < 4; i++) {
        __nv_bfloat162 p0 = __floats2bfloat162_rn(v[i].x * winv, v[i].y * winv);
        __nv_bfloat162 p1 = __floats2bfloat162_rn(v[i].z * winv, v[i].w * winv);
        uint2 u;
        u.x = *reinterpret_cast<uint32_t*>(&p0);
        u.y = *reinterpret_cast<uint32_t*>(&p1);
        reinterpret_cast<uint2*>(g_wb + (size_t)row * ND)[lane + i * 32] = u;
    }
}

// ---------------------------------------------------------------------------
// Kernel 3: bf16 mma.sync GEMM + exp-domain epilogue.
// grid = 782 (one CTA per 128-class chunk), block = 256 (8 warps, 4Mx2N).
// B tile [128 x 512] resident in smem; A streamed in 64-wide K tiles.
// ---------------------------------------------------------------------------
__device__ __forceinline__ void load_a_tile(uint32_t sA, int t, int buf, int tid) {
    const int msl = t >> 3;
    const int ks  = t & 7;
    #pragma unroll
    for (int i = 0; i < 8; i++) {
        int u = i * 256 + tid;      // 0..2047
        int r = u >> 3;             // 0..255
        int c = u & 7;              // 16B segment within 128B row
        uint32_t dst = sA + buf * A_STRIDE + r * A_ROW + c * 16;
        const void* src = g_fhat_b + (size_t)(msl * SLICE_M + r) * ND + ks * BK + c * 8;
        CP16(dst, src);
    }
}

__global__ void __launch_bounds__(256, 1) k_mma() {
    extern __shared__ char smem[];
    const uint32_t sB = smem_u32(smem);
    const uint32_t sA = sB + SZ_B;
    const int tid    = threadIdx.x;
    const int lane   = tid & 31;
    const int wid    = tid >> 5;
    const int warp_m = wid & 3;     // 0..3 (M)
    const int warp_n = wid >> 2;    // 0..1 (N)
    const int chunk  = blockIdx.x;
    const int colBase = chunk * BN;

    // ---- B tile load (once per CTA), grouped with A tile 0 ----
    #pragma unroll
    for (int i = 0; i < 32; i++) {
        int u = i * 256 + tid;      // 0..8191
        int r = u >> 6;             // 0..127 (class row)
        int c = u & 63;             // 16B segment within 1024B row
        uint32_t dst = sB + r * B_ROW + c * 16;
        const void* src = g_wb + (size_t)(colBase + r) * ND + c * 8;
        uint32_t sz = (colBase + r < NC) ? 16u : 0u;   // zero-fill OOB classes
        CP16Z(dst, src, sz);
    }
    load_a_tile(sA, 0, 0, tid);
    CP_COMMIT();

    float d[4][8][4];

    #pragma unroll 1
    for (int t = 0; t < NT; t++) {
        const int buf = t & 1;
        if (t + 1 < NT) {
            load_a_tile(sA, t + 1, buf ^ 1, tid);
            CP_COMMIT();
            asm volatile("cp.async.wait_group 1;" ::: "memory");
        } else {
            asm volatile("cp.async.wait_group 0;" ::: "memory");
        }
        __syncthreads();

        if ((t & 7) == 0) {
            #pragma unroll
            for (int mt = 0; mt < 4; mt++)
                #pragma unroll
                for (int nt = 0; nt < 8; nt++)
                    #pragma unroll
                    for (int j = 0; j < 4; j++) d[mt][nt][j] = 0.0f;
        }

        const uint32_t aBase = sA + buf * A_STRIDE;
        const int ksBase = (t & 7) * BK;
        #pragma unroll
        for (int kh = 0; kh < 4; kh++) {          // 4 x k16 within BK=64
            uint32_t a[4][4];
            #pragma unroll
            for (int mt = 0; mt < 4; mt++) {
                uint32_t addr = aBase
                    + (uint32_t)(warp_m * 64 + mt * 16 + (lane & 15)) * A_ROW
                    + (uint32_t)(kh * 16 + (lane >> 4) * 8) * 2;
                LDSM_X4(a[mt][0], a[mt][1], a[mt][2], a[mt][3], addr);
            }
            #pragma unroll
            for (int ng = 0; ng < 4; ng++) {      // 4 x n16 within warp's 64 cols
                uint32_t b0, b1, b2, b3;
                uint32_t addr = sB
                    + (uint32_t)(warp_n * 64 + ng * 16 + (lane & 7) + ((lane >> 4) << 3)) * B_ROW
                    + (uint32_t)(ksBase + kh * 16 + ((lane >> 3) & 1) * 8) * 2;
                LDSM_X4(b0, b1, b2, b3, addr);
                #pragma unroll
                for (int mt = 0; mt < 4; mt++) {
                    MMA_BF16(d[mt][ng * 2 + 0], a[mt], b0, b1);
                    MMA_BF16(d[mt][ng * 2 + 1], a[mt], b2, b3);
                }
            }
        }

        if ((t & 7) == 7) {
            // ---- epilogue for m-slice (t>>3): per-row sum of 2^(c*K1+K0) ----
            const int msl  = t >> 3;
            const int tcol = lane & 3;
            const int g    = lane >> 2;
            #pragma unroll
            for (int mt = 0; mt < 4; mt++) {
                float s0 = 0.0f, s1 = 0.0f;
                #pragma unroll
                for (int nt = 0; nt < 8; nt++) {
                    #pragma unroll
                    for (int j = 0; j < 4; j++) {
                        int colg = colBase + warp_n * 64 + nt * 8 + 2 * tcol + (j & 1);
                        float x = fmaf(d[mt][nt][j], K1, K0);
                        float e;
                        asm("ex2.approx.f32 %0, %1;" : "=f"(e) : "f"(x));
                        e = (colg < NC) ? e : 0.0f;
                        if (j < 2) s0 += e; else s1 += e;
                    }
                }
                s0 += __shfl_xor_sync(0xFFFFFFFFu, s0, 1);
                s0 += __shfl_xor_sync(0xFFFFFFFFu, s0, 2);
                s1 += __shfl_xor_sync(0xFFFFFFFFu, s1, 1);
                s1 += __shfl_xor_sync(0xFFFFFFFFu, s1, 2);
                if (tcol == 0) {
                    int rowg = msl * SLICE_M + warp_m * 64 + mt * 16 + g;
                    g_ps[warp_n][(size_t)rowg * NCHUNK + chunk] = s0;
                    g_ps[warp_n][(size_t)(rowg + 8) * NCHUNK + chunk] = s1;
                }
            }
        }
        __syncthreads();
    }
}

// ---------------------------------------------------------------------------
// Kernel 4: exact target cosine (fp32). grid=1024, block=128
// ---------------------------------------------------------------------------
__global__ void k_cost(const float* __restrict__ w, const int* __restrict__ tgt) {
    int b = blockIdx.x;
    int t = threadIdx.x;
    int c = tgt[b];
    float4 f = reinterpret_cast<const float4*>(g_fhat + (size_t)b * ND)[t];
    float4 ww = reinterpret_cast<const float4*>(w + (size_t)c * ND)[t];
    float d = f.x * ww.x + f.y * ww.y + f.z * ww.z + f.w * ww.w;
    #pragma unroll
    for (int o = 16; o; o >>= 1) d += __shfl_xor_sync(0xFFFFFFFFu, d, o);
    __shared__ float sw[4];
    if ((t & 31) == 0) sw[t >> 5] = d;
    __syncthreads();
    if (t == 0) {
        float tot = sw[0] + sw[1] + sw[2] + sw[3];
        g_cost[b] = tot * g_winv[c];
    }
}

// ---------------------------------------------------------------------------
// Kernel 5: sum partials -> LSE. grid=1024, block=256
// ---------------------------------------------------------------------------
__global__ void k_lse() {
    int row = blockIdx.x;
    int t = threadIdx.x;
    float s = 0.0f;
    for (int c = t; c < NCHUNK; c += 256)
        s += g_ps[0][(size_t)row * NCHUNK + c] + g_ps[1][(size_t)row * NCHUNK + c];
    #pragma unroll
    for (int o = 16; o; o >>= 1) s += __shfl_xor_sync(0xFFFFFFFFu, s, o);
    __shared__ float ss[8];
    if ((t & 31) == 0) ss[t >> 5] = s;
    __syncthreads();
    if (t == 0) {
        float tot = 0.0f;
        #pragma unroll
        for (int i = 0; i < 8; i++) tot += ss[i];
        g_lse[row] = S_SCALE + logf(tot);  // LSE of raw logits
    }
}

// ---------------------------------------------------------------------------
// Kernel 6: margin correction + CE mean. single block 256
// ---------------------------------------------------------------------------
__global__ void k_loss(float* __restrict__ out) {
    int t = threadIdx.x;
    float acc = 0.0f;
    for (int b = t; b < NB; b += 256) {
        float c = g_cost[b];
        float sine = sqrtf(fmaxf(1.0f - c * c, 0.0f));
        float phi = c * COS_M - sine * SIN_M;
        if (!(c > TH)) phi = c - MM;
        float L  = g_lse[b];
        float lt = S_SCALE * phi;
        float lc = S_SCALE * c;
        float corr = log1pf(expf(lt - L) - expf(lc - L));
        acc += (L + corr) - lt;
    }
    #pragma unroll
    for (int o = 16; o; o >>= 1) acc += __shfl_xor_sync(0xFFFFFFFFu, acc, o);
    __shared__ float sw[8];
    if ((t & 31) == 0) sw[t >> 5] = acc;
    __syncthreads();
    if (t == 0) {
        float tot = 0.0f;
        #pragma unroll
        for (int i = 0; i < 8; i++) tot += sw[i];
        out[0] = tot / (float)NB;
    }
}

// ---------------------------------------------------------------------------
extern "C" void kernel_launch(void* const* d_in, const int* in_sizes, int n_in,
                              void* d_out, int out_size) {
    const float* feat = (const float*)d_in[0];   // [1024, 512] f32
    const float* wt   = (const float*)d_in[1];   // [100000, 512] f32
    const int*   tgt  = (const int*)d_in[2];     // [1024] int32
    float* out = (float*)d_out;

    cudaFuncSetAttribute(k_mma, cudaFuncAttributeMaxDynamicSharedMemorySize, SM_TOTAL);

    k_norm_feat<<<NB, 128>>>(feat);
    k_wconv<<<(NC + 7) / 8, 256>>>(wt);
    k_mma<<<NCHUNK, 256, SM_TOTAL>>>();
    k_cost<<<NB, 128>>>(wt, tgt);
    k_lse<<<NB, 256>>>();
    k_loss<<<1, 256>>>(out);
}